// round 4
// baseline (speedup 1.0000x reference)
#include <cuda_runtime.h>
#include <cuda_bf16.h>
#include <math.h>

#define HDIM 64
#define KDIM 256
#define HW   65536
#define NPTS 262144
#define RATE_F 0.999f
#define EPS_F  1e-6f

typedef unsigned long long u64;

// Persistent device scratch (allocation-free rule).
__device__ __align__(16) float g_m  [KDIM * HDIM];
__device__ __align__(16) float g_mn [KDIM * HDIM];
__device__ __align__(16) float g_sum[KDIM * HDIM];
__device__ float g_cnt[KDIM];
__device__ float g_nrm[KDIM];

// ---- packed f32x2 helpers (FFMA2: 2 FMAs / instruction on sm_103a) ----
__device__ __forceinline__ u64 pack2(float lo, float hi) {
    u64 r; asm("mov.b64 %0, {%1, %2};" : "=l"(r) : "f"(lo), "f"(hi)); return r;
}
__device__ __forceinline__ void unpack2(u64 v, float& lo, float& hi) {
    asm("mov.b64 {%0, %1}, %2;" : "=f"(lo), "=f"(hi) : "l"(v));
}
__device__ __forceinline__ void fma2(u64& d, u64 a, u64 b) {
    asm("fma.rn.f32x2 %0, %1, %2, %0;" : "+l"(d) : "l"(a), "l"(b));
}

// ---------------------------------------------------------------------------
// prep: m = units; mn = normalize(m); nrm = |m|; zero sums/counts.
// ---------------------------------------------------------------------------
__global__ void prep_kernel(const float* __restrict__ units) {
    int warp = threadIdx.x >> 5, lane = threadIdx.x & 31;
    int k = blockIdx.x * 8 + warp;
    if (k >= KDIM) return;
    float v0 = units[k * HDIM + lane];
    float v1 = units[k * HDIM + 32 + lane];
    g_m[k * HDIM + lane]      = v0;
    g_m[k * HDIM + 32 + lane] = v1;
    float ssq = v0 * v0 + v1 * v1;
    #pragma unroll
    for (int o = 16; o; o >>= 1) ssq += __shfl_xor_sync(0xFFFFFFFFu, ssq, o);
    float nrm = sqrtf(ssq);
    float inv = 1.0f / fmaxf(nrm, 1e-12f);
    g_mn[k * HDIM + lane]      = v0 * inv;
    g_mn[k * HDIM + 32 + lane] = v1 * inv;
    g_sum[k * HDIM + lane]      = 0.0f;
    g_sum[k * HDIM + 32 + lane] = 0.0f;
    if (lane == 0) { g_cnt[k] = 0.0f; g_nrm[k] = nrm; }
}

// ---------------------------------------------------------------------------
// assign: 2 points/thread, argmax over k of (xf . mn_k), scatter EMA sums.
// grid = NPTS/512 CTAs x 256 threads. dyn smem = 64 KB (mn).
// ---------------------------------------------------------------------------
__global__ void __launch_bounds__(256) assign_kernel(const float* __restrict__ x) {
    extern __shared__ ulonglong2 smq[];          // 4096 x 16B = mn tile
    const ulonglong2* gm = (const ulonglong2*)g_mn;
    #pragma unroll 4
    for (int i = threadIdx.x; i < KDIM * HDIM / 4; i += 256) smq[i] = gm[i];
    __syncthreads();

    int t  = blockIdx.x * 256 + threadIdx.x;
    int p0 = t, p1 = t + NPTS / 2;
    int b0 = p0 >> 16, b1 = p1 >> 16;
    const float* xa_p = x + (size_t)b0 * HDIM * HW + (p0 & (HW - 1));
    const float* xb_p = x + (size_t)b1 * HDIM * HW + (p1 & (HW - 1));

    u64 xa[HDIM / 2], xb[HDIM / 2];
    #pragma unroll
    for (int i = 0; i < HDIM / 2; i++) {
        xa[i] = pack2(xa_p[(size_t)(2 * i) * HW], xa_p[(size_t)(2 * i + 1) * HW]);
        xb[i] = pack2(xb_p[(size_t)(2 * i) * HW], xb_p[(size_t)(2 * i + 1) * HW]);
    }

    float bestA = -1e30f, bestB = -1e30f;
    int   biA = 0, biB = 0;
    for (int k = 0; k < KDIM; k++) {
        u64 da0 = 0ull, da1 = 0ull, db0 = 0ull, db1 = 0ull;  // {0,0} packed
        const ulonglong2* row = smq + k * 16;
        #pragma unroll
        for (int i = 0; i < 16; i++) {
            ulonglong2 q = row[i];
            fma2(da0, xa[2 * i],     q.x);
            fma2(da1, xa[2 * i + 1], q.y);
            fma2(db0, xb[2 * i],     q.x);
            fma2(db1, xb[2 * i + 1], q.y);
        }
        float a0, a1, a2, a3, c0, c1, c2, c3;
        unpack2(da0, a0, a1); unpack2(da1, a2, a3);
        unpack2(db0, c0, c1); unpack2(db1, c2, c3);
        float dA = (a0 + a1) + (a2 + a3);
        float dB = (c0 + c1) + (c2 + c3);
        if (dA > bestA) { bestA = dA; biA = k; }
        if (dB > bestB) { bestB = dB; biB = k; }
    }

    float* dstA = g_sum + biA * HDIM;
    #pragma unroll
    for (int i = 0; i < 16; i++) {
        float f0, f1, f2, f3;
        unpack2(xa[2 * i], f0, f1); unpack2(xa[2 * i + 1], f2, f3);
        asm volatile("red.global.add.v4.f32 [%0], {%1,%2,%3,%4};"
                     :: "l"(dstA + 4 * i), "f"(f0), "f"(f1), "f"(f2), "f"(f3) : "memory");
    }
    atomicAdd(g_cnt + biA, 1.0f);

    float* dstB = g_sum + biB * HDIM;
    #pragma unroll
    for (int i = 0; i < 16; i++) {
        float f0, f1, f2, f3;
        unpack2(xb[2 * i], f0, f1); unpack2(xb[2 * i + 1], f2, f3);
        asm volatile("red.global.add.v4.f32 [%0], {%1,%2,%3,%4};"
                     :: "l"(dstB + 4 * i), "f"(f0), "f"(f1), "f"(f2), "f"(f3) : "memory");
    }
    atomicAdd(g_cnt + biB, 1.0f);
}

// ---------------------------------------------------------------------------
// update: m = m*RATE + (sum/(cnt+eps))*(1-RATE); refresh mn, nrm; zero sums.
// ---------------------------------------------------------------------------
__global__ void update_kernel() {
    int warp = threadIdx.x >> 5, lane = threadIdx.x & 31;
    int k = blockIdx.x * 8 + warp;
    if (k >= KDIM) return;
    const float IR = 1.0f - RATE_F;
    float sc = IR / (g_cnt[k] + EPS_F);
    float m0 = g_m[k * HDIM + lane]      * RATE_F + g_sum[k * HDIM + lane]      * sc;
    float m1 = g_m[k * HDIM + 32 + lane] * RATE_F + g_sum[k * HDIM + 32 + lane] * sc;
    g_m[k * HDIM + lane]      = m0;
    g_m[k * HDIM + 32 + lane] = m1;
    float ssq = m0 * m0 + m1 * m1;
    #pragma unroll
    for (int o = 16; o; o >>= 1) ssq += __shfl_xor_sync(0xFFFFFFFFu, ssq, o);
    float nrm = sqrtf(ssq);
    float inv = 1.0f / fmaxf(nrm, 1e-12f);
    g_mn[k * HDIM + lane]      = m0 * inv;
    g_mn[k * HDIM + 32 + lane] = m1 * inv;
    g_sum[k * HDIM + lane]      = 0.0f;
    g_sum[k * HDIM + 32 + lane] = 0.0f;
    if (lane == 0) { g_cnt[k] = 0.0f; g_nrm[k] = nrm; }
}

// ---------------------------------------------------------------------------
// out: single pass (score in [-1,1] => exp safe without max-shift).
// m_k reconstructed as mn_k * nrm_k so one mn row load serves dot AND acc.
// dyn smem = 64 KB mn + 1 KB nrm. grid = NPTS/256 x 256.
// ---------------------------------------------------------------------------
__global__ void __launch_bounds__(256, 1) out_kernel(const float* __restrict__ x,
                                                     float* __restrict__ out) {
    extern __shared__ ulonglong2 smem_raw[];
    ulonglong2* smq = smem_raw;                                  // mn: 4096 x 16B
    float* snrm = (float*)(smem_raw + KDIM * HDIM / 4);          // nrm: 256 floats
    const ulonglong2* gm = (const ulonglong2*)g_mn;
    #pragma unroll 4
    for (int i = threadIdx.x; i < KDIM * HDIM / 4; i += 256) smq[i] = gm[i];
    if (threadIdx.x < KDIM) snrm[threadIdx.x] = g_nrm[threadIdx.x];
    __syncthreads();

    int p  = blockIdx.x * 256 + threadIdx.x;
    int b  = p >> 16;
    const float* xb = x + (size_t)b * HDIM * HW + (p & (HW - 1));

    u64 xr[HDIM / 2];
    float s0 = 0.f, s1 = 0.f;
    #pragma unroll
    for (int i = 0; i < HDIM / 2; i++) {
        float f0 = xb[(size_t)(2 * i) * HW];
        float f1 = xb[(size_t)(2 * i + 1) * HW];
        xr[i] = pack2(f0, f1);
        s0 = fmaf(f0, f0, s0);
        s1 = fmaf(f1, f1, s1);
    }
    float invn = 1.0f / fmaxf(sqrtf(s0 + s1), 1e-12f);

    u64 acc[HDIM / 2];
    #pragma unroll
    for (int i = 0; i < HDIM / 2; i++) acc[i] = 0ull;
    float den = 0.0f;

    for (int k = 0; k < KDIM; k++) {
        u64 v[HDIM / 2];
        const ulonglong2* row = smq + k * 16;
        #pragma unroll
        for (int i = 0; i < 16; i++) { ulonglong2 q = row[i]; v[2 * i] = q.x; v[2 * i + 1] = q.y; }

        u64 d0 = 0ull, d1 = 0ull;
        #pragma unroll
        for (int i = 0; i < 16; i++) {
            fma2(d0, xr[2 * i],     v[2 * i]);
            fma2(d1, xr[2 * i + 1], v[2 * i + 1]);
        }
        float e0, e1, e2, e3;
        unpack2(d0, e0, e1); unpack2(d1, e2, e3);
        float d = (e0 + e1) + (e2 + e3);
        float e = __expf(d * invn);
        den += e;
        u64 w2 = pack2(e * snrm[k], e * snrm[k]);
        #pragma unroll
        for (int i = 0; i < HDIM / 2; i++) fma2(acc[i], w2, v[i]);
    }

    float iden = 1.0f / den;
    float* ob = out + (size_t)b * HDIM * HW + (p & (HW - 1));
    #pragma unroll
    for (int i = 0; i < HDIM / 2; i++) {
        float f0, f1;
        unpack2(acc[i], f0, f1);
        ob[(size_t)(2 * i) * HW]     = f0 * iden;
        ob[(size_t)(2 * i + 1) * HW] = f1 * iden;
    }
}

// ---------------------------------------------------------------------------
extern "C" void kernel_launch(void* const* d_in, const int* in_sizes, int n_in,
                              void* d_out, int out_size) {
    const float* x;
    const float* units;
    if (in_sizes[0] >= in_sizes[1]) { x = (const float*)d_in[0]; units = (const float*)d_in[1]; }
    else                            { x = (const float*)d_in[1]; units = (const float*)d_in[0]; }
    float* out = (float*)d_out;

    const int mn_bytes  = KDIM * HDIM * (int)sizeof(float);          // 64 KB
    const int out_bytes = mn_bytes + KDIM * (int)sizeof(float);     // 65 KB
    cudaFuncSetAttribute(assign_kernel, cudaFuncAttributeMaxDynamicSharedMemorySize, mn_bytes);
    cudaFuncSetAttribute(out_kernel,    cudaFuncAttributeMaxDynamicSharedMemorySize, out_bytes);

    prep_kernel<<<32, 256>>>(units);
    for (int it = 0; it < 3; it++) {
        assign_kernel<<<NPTS / 512, 256, mn_bytes>>>(x);
        update_kernel<<<32, 256>>>();
    }
    out_kernel<<<NPTS / 256, 256, out_bytes>>>(x, out);
}